// round 8
// baseline (speedup 1.0000x reference)
#include <cuda_runtime.h>
#include <cuda_fp16.h>
#include <cstdint>

// Problem constants (fixed by the reference)
#define Bc 128
#define Tc 30
#define Nc 10000
#define Mc 5000
#define Kc 10
#define CHK_W 6
#define OBS_W 50
#define EPSc 1e-6f

#define NTH   1024
#define NPROD 384            // warps 0-11: producers
#define NCONS 640            // warps 12-31: consumers
#define RPC   4              // rows per chunk
#define NCH   8              // chunks per b (last has 2 rows)
#define NQ    2500           // float4 groups per row
#define NTASKS (Bc * NCH)    // 1024 tasks
#define GRID  148            // persistent: one CTA per SM

// (128/127)^6 and (128/127)^50 de-scaling constants
#define SC6   1.04818341f
#define SC50  1.48016639f

// named barrier ids
#define BFULL0 2
#define BFULL1 3
#define BFREE0 4
#define BFREE1 5

// Shared memory layout (bytes)
// table: uint per position = 4 rows of biased-u8 tanh
#define OFF_BUF0 0
#define SZ_BUF   (Nc * 4)                    // 40000
#define OFF_BUF1 (OFF_BUF0 + SZ_BUF)         // 40000
#define OFF_CA   (OFF_BUF1 + SZ_BUF)         // 80000: u16 pair (i0,i1) per check
#define OFF_CB   (OFF_CA + Mc * 4)           // 100000: (i2,i3)
#define OFF_CC   (OFF_CB + Mc * 4)           // 120000: (i4,i5)
#define OFF_OIDX (OFF_CC + Mc * 4)           // 140000: u16[500]
#define OFF_RED  ((OFF_OIDX + Kc * OBS_W * 2 + 15) & ~15)
#define SMEM_BYTES (OFF_RED + 128)           // ~141136

__device__ double g_acc = 0.0;
__device__ unsigned int g_cnt = 0;

__device__ __forceinline__ __half2 H2(unsigned int u) {
    return *reinterpret_cast<const __half2*>(&u);
}
__device__ __forceinline__ unsigned int U2(__half2 h) {
    return *reinterpret_cast<const unsigned int*>(&h);
}
__device__ __forceinline__ unsigned int tanh_h2_u(__half2 v) {
    unsigned int r, x = U2(v);
    asm("tanh.approx.f16x2 %0, %1;" : "=r"(r) : "r"(x));
    return r;
}
__device__ __forceinline__ void bar_sync(int id) {
    asm volatile("bar.sync %0, %1;" :: "r"(id), "n"(NTH) : "memory");
}
__device__ __forceinline__ void bar_arrive(int id) {
    asm volatile("bar.arrive %0, %1;" :: "r"(id), "n"(NTH) : "memory");
}

// ---- encode: rows (a,b) f32 -> f16x2 word holding integers 1152+round(127*t)
__device__ __forceinline__ unsigned int enc_pair(float a, float b) {
    const __half2 h05  = __float2half2_rn(0.5f);
    const __half2 k127 = __float2half2_rn(127.0f);
    const __half2 b1152= __float2half2_rn(1152.0f);
    __half2 t = H2(tanh_h2_u(__hmul2(__floats2half2_rn(a, b), h05)));
    return U2(__hfma2(t, k127, b1152));   // halves in [1025,1279], integer-valued
}

// ---- decode: u32 of 4 biased bytes -> two half2 of t*127/128
#define CK   0x64646464u
__device__ __forceinline__ __half2 dec_lo(unsigned int a) {
    const __half2 mk = __float2half2_rn(0.0078125f);   // 2^-7
    const __half2 mb = __float2half2_rn(-9.0f);
    return __hfma2(H2(__byte_perm(a, CK, 0x4140)), mk, mb);
}
__device__ __forceinline__ __half2 dec_hi(unsigned int a) {
    const __half2 mk = __float2half2_rn(0.0078125f);
    const __half2 mb = __float2half2_rn(-9.0f);
    return __hfma2(H2(__byte_perm(a, CK, 0x4342)), mk, mb);
}

__global__ __launch_bounds__(NTH, 1)
void decode_loss_kernel(const float* __restrict__ llrs,
                        const int* __restrict__ syndromes,
                        const int* __restrict__ observables,
                        const int* __restrict__ chk_idx,
                        const int* __restrict__ obs_idx,
                        float* __restrict__ out) {
    extern __shared__ char smem[];
    unsigned int*   buf0 = (unsigned int*)(smem + OFF_BUF0);
    unsigned int*   buf1 = (unsigned int*)(smem + OFF_BUF1);
    unsigned int*   cA   = (unsigned int*)(smem + OFF_CA);
    unsigned int*   cB   = (unsigned int*)(smem + OFF_CB);
    unsigned int*   cC   = (unsigned int*)(smem + OFF_CC);
    unsigned short* oidx = (unsigned short*)(smem + OFF_OIDX);
    float*          red  = (float*)(smem + OFF_RED);

    const int cta = blockIdx.x;
    const int tid = threadIdx.x;
    const int ntasks = (NTASKS - cta + GRID - 1) / GRID;

    // ---- Stage (once per CTA): SoA u16-pair index arrays ----
    for (int m = tid; m < Mc; m += NTH) {
        const int2* c6 = (const int2*)(chk_idx + 6 * m);
        int2 p0 = __ldg(&c6[0]);
        int2 p1 = __ldg(&c6[1]);
        int2 p2 = __ldg(&c6[2]);
        cA[m] = (unsigned int)p0.x | ((unsigned int)p0.y << 16);
        cB[m] = (unsigned int)p1.x | ((unsigned int)p1.y << 16);
        cC[m] = (unsigned int)p2.x | ((unsigned int)p2.y << 16);
    }
    for (int i = tid; i < Kc * OBS_W; i += NTH)
        oidx[i] = (unsigned short)__ldg(&obs_idx[i]);
    __syncthreads();

    float acc = 0.0f;

    if (tid < NPROD) {
        // ================= PRODUCER (12 warps) =================
        const int tp = tid;
        for (int k = 0; k < ntasks; k++) {
            const int task = cta + k * GRID;
            const int b    = task >> 3;
            const int c    = task & 7;
            const int rows = min(RPC, Tc - RPC * c);
            if (k >= 2) bar_sync(BFREE0 + (k & 1));
            uint4* bf4 = (uint4*)((k & 1) ? buf1 : buf0);
            const float4* rb = (const float4*)(llrs + ((size_t)b * Tc + (size_t)RPC * c) * Nc);

            for (int q = tp; q < NQ; q += NPROD) {
                const float4 z = make_float4(0.f, 0.f, 0.f, 0.f);
                float4 v0 =              __ldg(&rb[0 * NQ + q]);
                float4 v1 = (rows > 1) ? __ldg(&rb[1 * NQ + q]) : z;
                float4 v2 = (rows > 2) ? __ldg(&rb[2 * NQ + q]) : z;
                float4 v3 = (rows > 3) ? __ldg(&rb[3 * NQ + q]) : z;

                unsigned int w01x = enc_pair(v0.x, v1.x), w23x = enc_pair(v2.x, v3.x);
                unsigned int w01y = enc_pair(v0.y, v1.y), w23y = enc_pair(v2.y, v3.y);
                unsigned int w01z = enc_pair(v0.z, v1.z), w23z = enc_pair(v2.z, v3.z);
                unsigned int w01w = enc_pair(v0.w, v1.w), w23w = enc_pair(v2.w, v3.w);

                uint4 o;
                o.x = __byte_perm(w01x, w23x, 0x6420);   // pos 4q+0: rows0-3 bytes
                o.y = __byte_perm(w01y, w23y, 0x6420);
                o.z = __byte_perm(w01z, w23z, 0x6420);
                o.w = __byte_perm(w01w, w23w, 0x6420);
                bf4[q] = o;
            }
            bar_arrive(BFULL0 + (k & 1));
        }
    } else {
        // ================= CONSUMER (20 warps) =================
        const int tc = tid - NPROD;
        for (int k = 0; k < ntasks; k++) {
            const int task = cta + k * GRID;
            const int b    = task >> 3;
            bar_sync(BFULL0 + (k & 1));
            const unsigned int* buf = (k & 1) ? buf1 : buf0;
            const int* syn = syndromes + (size_t)b * Mc;

            #pragma unroll 2
            for (int m = tc; m < Mc; m += NCONS) {
                unsigned int iA = cA[m];
                unsigned int iB = cB[m];
                unsigned int iC = cC[m];
                unsigned int g0 = buf[iA & 0xFFFF];
                unsigned int g1 = buf[iA >> 16];
                unsigned int g2 = buf[iB & 0xFFFF];
                unsigned int g3 = buf[iB >> 16];
                unsigned int g4 = buf[iC & 0xFFFF];
                unsigned int g5 = buf[iC >> 16];
                const float s  = 1.0f - 2.0f * (float)__ldg(&syn[m]);
                const float sc = s * SC6;

                __half2 p01 = __hmul2(__hmul2(dec_lo(g0), dec_lo(g1)),
                              __hmul2(__hmul2(dec_lo(g2), dec_lo(g3)),
                                      __hmul2(dec_lo(g4), dec_lo(g5))));
                __half2 p23 = __hmul2(__hmul2(dec_hi(g0), dec_hi(g1)),
                              __hmul2(__hmul2(dec_hi(g2), dec_hi(g3)),
                                      __hmul2(dec_hi(g4), dec_hi(g5))));

                float2 f0 = __half22float2(p01);
                float2 f1 = __half22float2(p23);
                float a0 = fmaxf(fmaf(sc, f0.x, 1.0f), EPSc);
                float a1 = fmaxf(fmaf(sc, f0.y, 1.0f), EPSc);
                float a2 = fmaxf(fmaf(sc, f1.x, 1.0f), EPSc);
                float a3 = fmaxf(fmaf(sc, f1.y, 1.0f), EPSc);
                acc += __log2f((a0 * a1) * (a2 * a3));
            }

            if (tc < Kc) {
                const __half2 one2 = __float2half2_rn(1.0f);
                __half2 p01 = one2, p23 = one2;
                #pragma unroll
                for (int j = 0; j < OBS_W; j++) {
                    unsigned int g = buf[oidx[tc * OBS_W + j]];
                    p01 = __hmul2(p01, dec_lo(g));
                    p23 = __hmul2(p23, dec_hi(g));
                }
                const float s  = 1.0f - 2.0f * (float)__ldg(&observables[(size_t)b * Kc + tc]);
                const float sc = s * SC50;
                float2 f0 = __half22float2(p01);
                float2 f1 = __half22float2(p23);
                float a0 = fmaxf(fmaf(sc, f0.x, 1.0f), EPSc);
                float a1 = fmaxf(fmaf(sc, f0.y, 1.0f), EPSc);
                float a2 = fmaxf(fmaf(sc, f1.x, 1.0f), EPSc);
                float a3 = fmaxf(fmaf(sc, f1.y, 1.0f), EPSc);
                acc += __log2f((a0 * a1) * (a2 * a3));
            }

            if (k < ntasks - 2) bar_arrive(BFREE0 + (k & 1));
        }
    }

    // ---- Block reduction (producers contribute 0) ----
    __syncthreads();
    float v = acc;
    #pragma unroll
    for (int o = 16; o; o >>= 1) v += __shfl_down_sync(0xFFFFFFFFu, v, o);
    const int wid = tid >> 5, lane = tid & 31;
    if (lane == 0) red[wid] = v;
    __syncthreads();
    if (wid == 0) {
        float w = (lane < NTH / 32) ? red[lane] : 0.0f;
        #pragma unroll
        for (int o = 16; o; o >>= 1) w += __shfl_down_sync(0xFFFFFFFFu, w, o);
        if (lane == 0) atomicAdd(&g_acc, (double)w);
    }

    // ---- Last-block-done: finalize + self-reset (graph-replayable) ----
    if (tid == 0) {
        __threadfence();
        unsigned int prev = atomicAdd(&g_cnt, 1u);
        if (prev == GRID - 1) {
            __threadfence();
            double S = *((volatile double*)&g_acc);
            // loss = 0.5*ln2*((M+K) - S/(B*T))
            double loss = 0.5 * 0.6931471805599453
                        * ((double)(Mc + Kc) - S / ((double)Bc * (double)Tc));
            out[0] = (float)loss;
            *((volatile double*)&g_acc) = 0.0;
            *((volatile unsigned int*)&g_cnt) = 0u;
            __threadfence();
        }
    }
}

extern "C" void kernel_launch(void* const* d_in, const int* in_sizes, int n_in,
                              void* d_out, int out_size) {
    const float* llrs        = (const float*)d_in[0];
    const int*   syndromes   = (const int*)d_in[1];
    const int*   observables = (const int*)d_in[2];
    const int*   chk_idx     = (const int*)d_in[3];
    // d_in[4] = chk_seg (unused: layout implied), d_in[5] = obs_idx, d_in[6] = obs_seg
    const int*   obs_idx     = (const int*)d_in[5];
    float* out = (float*)d_out;

    cudaFuncSetAttribute(decode_loss_kernel,
                         cudaFuncAttributeMaxDynamicSharedMemorySize, SMEM_BYTES);

    decode_loss_kernel<<<GRID, NTH, SMEM_BYTES>>>(
        llrs, syndromes, observables, chk_idx, obs_idx, out);
}